// round 4
// baseline (speedup 1.0000x reference)
#include <cuda_runtime.h>
#include <cstdint>

// Problem constants (fixed by setup_inputs)
#define TOKENS 16384   // B*L = 8*2048
#define DIM    1024    // D
#define CD     16      // codebook dim
#define CS     8192    // codebook size

// Input element counts (all distinct -> bind pointers by size)
#define N_X  (TOKENS * DIM)   // 16777216
#define N_W  (CD * DIM)       // 16384
#define N_CB (CS * CD)        // 131072

#define P2_THREADS 256
#define P2_CODES   512                         // codes per smem chunk
#define NSPLIT     (CS / P2_CODES)             // 16
#define P2_TILES   (TOKENS / (P2_THREADS * 2)) // 32 (2 tokens/thread)

__device__ __align__(16) float g_z[TOKENS * CD];
__device__ float g_hbneg[CS];                  // -0.5 * ||c||^2
__device__ float g_bval[NSPLIT][TOKENS];
__device__ int   g_bidx[NSPLIT][TOKENS];

// ---------------- kernel 0: -0.5*||c||^2 ----------------
__global__ void prep_kernel(const float* __restrict__ cb) {
    int k = blockIdx.x * blockDim.x + threadIdx.x;
    if (k < CS) {
        float s = 0.f;
#pragma unroll
        for (int i = 0; i < CD; i++) {
            float v = cb[(size_t)k * CD + i];
            s = fmaf(v, v, s);
        }
        g_hbneg[k] = -0.5f * s;
    }
}

// ---------------- kernel 1: projection + LayerNorm ----------------
#define P1_BLOCK  128
#define P1_DCHUNK 64
#define P1_XPAD   65

__global__ void __launch_bounds__(P1_BLOCK)
proj_ln_kernel(const float* __restrict__ x, const float* __restrict__ W) {
    __shared__ float xs[P1_BLOCK * P1_XPAD];             // 33.3 KB
    __shared__ float wt[P1_DCHUNK][CD];                  // 4 KB

    const int tid = threadIdx.x;
    const int tokBase = blockIdx.x * P1_BLOCK;

    float z[CD];
#pragma unroll
    for (int c = 0; c < CD; c++) z[c] = 0.f;

    for (int dB = 0; dB < DIM; dB += P1_DCHUNK) {
        __syncthreads();
        // stage W chunk transposed: wt[d][c] = W[c, dB+d]
        for (int i = tid; i < P1_DCHUNK * CD; i += P1_BLOCK) {
            int d = i >> 4, c = i & 15;
            wt[d][c] = W[c * DIM + dB + d];
        }
        // stage x tile: 128 tokens x 64 floats (coalesced, padded rows)
        for (int it = 0; it < 16; it++) {
            int i = it * P1_BLOCK + tid;          // 0..2047
            int row = i >> 4;
            int col = (i & 15) << 2;
            const float* src = x + (size_t)(tokBase + row) * DIM + dB + col;
            float* dst = xs + row * P1_XPAD + col;
            dst[0] = src[0]; dst[1] = src[1]; dst[2] = src[2]; dst[3] = src[3];
        }
        __syncthreads();

        const float* xr = xs + tid * P1_XPAD;
#pragma unroll 8
        for (int d = 0; d < P1_DCHUNK; d++) {
            float xv = xr[d];
#pragma unroll
            for (int c = 0; c < CD; c++)
                z[c] = fmaf(xv, wt[d][c], z[c]);
        }
    }

    // LayerNorm over 16 dims, no affine, eps = 1e-5
    float mu = 0.f;
#pragma unroll
    for (int c = 0; c < CD; c++) mu += z[c];
    mu *= (1.0f / CD);
    float var = 0.f;
#pragma unroll
    for (int c = 0; c < CD; c++) { float t = z[c] - mu; var = fmaf(t, t, var); }
    var *= (1.0f / CD);
    float inv = rsqrtf(var + 1e-5f);

    float* o = g_z + (size_t)(tokBase + tid) * CD;
#pragma unroll
    for (int c = 0; c < CD; c++) o[c] = (z[c] - mu) * inv;
}

// ---------------- kernel 2: code scan (argmax of z.c - 0.5||c||^2) ----------------
__global__ void __launch_bounds__(P2_THREADS)
scan_kernel(const float* __restrict__ cb) {
    __shared__ float csm[P2_CODES * CD];   // 32 KB
    __shared__ float hb[P2_CODES];         // 2 KB

    const int tile  = blockIdx.x;
    const int split = blockIdx.y;
    const int kBase = split * P2_CODES;

    for (int i = threadIdx.x; i < P2_CODES * CD; i += P2_THREADS)
        csm[i] = cb[(size_t)kBase * CD + i];
    for (int i = threadIdx.x; i < P2_CODES; i += P2_THREADS)
        hb[i] = g_hbneg[kBase + i];
    __syncthreads();

    const int t0 = tile * (P2_THREADS * 2) + threadIdx.x;
    const int t1 = t0 + P2_THREADS;

    float z0[CD], z1[CD];
#pragma unroll
    for (int c = 0; c < CD; c++) {
        z0[c] = g_z[(size_t)t0 * CD + c];
        z1[c] = g_z[(size_t)t1 * CD + c];
    }

    float best0 = -3.0e38f, best1 = -3.0e38f;
    int bi0 = 0, bi1 = 0;

#pragma unroll 4
    for (int k = 0; k < P2_CODES; k++) {
        const float* ck = csm + k * CD;
        float s0 = hb[k];
        float s1 = hb[k];
#pragma unroll
        for (int c = 0; c < CD; c++) {
            float cv = ck[c];
            s0 = fmaf(z0[c], cv, s0);
            s1 = fmaf(z1[c], cv, s1);
        }
        if (s0 > best0) { best0 = s0; bi0 = k; }   // strict > : first index wins ties
        if (s1 > best1) { best1 = s1; bi1 = k; }
    }

    g_bval[split][t0] = best0;
    g_bidx[split][t0] = kBase + bi0;
    g_bval[split][t1] = best1;
    g_bidx[split][t1] = kBase + bi1;
}

// ---------------- kernel 3: combine splits ----------------
// NOTE: output written as float32 (codes are small ints, exactly representable).
__global__ void combine_kernel(float* __restrict__ out) {
    int t = blockIdx.x * blockDim.x + threadIdx.x;
    if (t < TOKENS) {
        float best = -3.0e38f;
        int bi = 0;
#pragma unroll
        for (int s = 0; s < NSPLIT; s++) {        // ascending code order
            float v = g_bval[s][t];
            int   i = g_bidx[s][t];
            if (v > best) { best = v; bi = i; }
        }
        out[t] = (float)bi;
    }
}

// ---------------- launch ----------------
extern "C" void kernel_launch(void* const* d_in, const int* in_sizes, int n_in,
                              void* d_out, int out_size) {
    const float* x  = nullptr;
    const float* W  = nullptr;
    const float* cb = nullptr;
    for (int i = 0; i < n_in; i++) {
        // elements-denominated sizes
        if      (in_sizes[i] == N_X)  x  = (const float*)d_in[i];
        else if (in_sizes[i] == N_W)  W  = (const float*)d_in[i];
        else if (in_sizes[i] == N_CB) cb = (const float*)d_in[i];
        // bytes-denominated fallback (4x)
        else if (in_sizes[i] == 4 * N_X)  x  = (const float*)d_in[i];
        else if (in_sizes[i] == 4 * N_W)  W  = (const float*)d_in[i];
        else if (in_sizes[i] == 4 * N_CB) cb = (const float*)d_in[i];
    }
    if (!x)  x  = (const float*)d_in[0];
    if (!W)  W  = (const float*)d_in[1];
    if (!cb) cb = (const float*)d_in[2];

    float* out = (float*)d_out;                    // (8,2048) as float32

    prep_kernel<<<CS / 256, 256>>>(cb);
    proj_ln_kernel<<<TOKENS / P1_BLOCK, P1_BLOCK>>>(x, W);
    dim3 g2(P2_TILES, NSPLIT);
    scan_kernel<<<g2, P2_THREADS>>>(cb);
    combine_kernel<<<(TOKENS + 255) / 256, 256>>>(out);
}